// round 1
// baseline (speedup 1.0000x reference)
#include <cuda_runtime.h>
#include <math.h>
#include <stdint.h>

// ---------------- static problem shape (from setup_inputs) ----------------
#define N_TOK   12288
#define BATCH   64
#define MAXD    256
#define DEV     448
#define PE_DIM  64
#define EMB     512
#define IN_DIM  512            // DEV + PE_DIM
#define NH      8
#define HD      64
#define ROWS    (BATCH*MAXD)   // 16384 padded rows
#define QKV_DIM (3*EMB)        // 1536
#define LN_EPS  1e-5f

// ---------------- scratch (static device globals; no allocs) ----------------
__device__ float g_x    [(size_t)N_TOK*IN_DIM];
__device__ float g_emb  [(size_t)N_TOK*EMB];
__device__ float g_dense[(size_t)ROWS*EMB];
__device__ float g_qkv  [(size_t)ROWS*QKV_DIM];
__device__ float g_scores[(size_t)BATCH*NH*MAXD*MAXD];
__device__ float g_ctx  [(size_t)ROWS*EMB];
__device__ float g_mha  [(size_t)ROWS*EMB];
__device__ float g_norm [(size_t)ROWS*EMB];

// ---------------- helpers ----------------
__device__ __forceinline__ int find_batch(const int* __restrict__ si, int n) {
    int lo = 0, hi = BATCH;
    while (hi - lo > 1) {
        int mid = (lo + hi) >> 1;
        if (__ldg(&si[mid]) <= n) lo = mid; else hi = mid;
    }
    return lo;
}

// ---------------- 1. build x = [states | PE] ----------------
__global__ void build_x(const float* __restrict__ states, const int* __restrict__ si) {
    int idx = blockIdx.x * blockDim.x + threadIdx.x;
    if (idx >= N_TOK * IN_DIM) return;
    int n = idx / IN_DIM, c = idx - n * IN_DIM;
    float v;
    if (c < DEV) {
        v = states[(size_t)n * DEV + c];
    } else {
        int b = find_batch(si, n);
        int pos = n - __ldg(&si[b]) + 1;             // 1-based
        int j = c - DEV;
        int i2 = (j >> 1) << 1;                      // 0,0,2,2,4,4,...
        float freq = expf((float)i2 * (-9.210340371976184f / (float)PE_DIM));
        float ang = (float)pos * freq;
        v = (j & 1) ? cosf(ang) : sinf(ang);
    }
    g_x[idx] = v;
}

// ---------------- 2/4/8. generic NT GEMM: C = act(A * B^T + bias) ----------------
// 128x128 block tile, BK=16, 256 threads, 8x8 micro-tile.
// WHICH selects scratch A/C:  0: g_x->g_emb   1: g_dense->g_qkv   2: g_ctx->g_mha
template<int ACT, int WHICH>
__global__ __launch_bounds__(256) void gemm_nt(const float* __restrict__ B,
                                               const float* __restrict__ bias,
                                               int M, int Nn, int K) {
    const float* A = (WHICH == 0) ? g_x : (WHICH == 1) ? g_dense : g_ctx;
    float*       C = (WHICH == 0) ? g_emb : (WHICH == 1) ? g_qkv : g_mha;

    __shared__ float As[16][128];
    __shared__ float Bs[16][128];

    int m0 = blockIdx.y * 128;
    int n0 = blockIdx.x * 128;
    int tid = threadIdx.x;
    int tx = tid & 15, ty = tid >> 4;

    float acc[8][8];
    #pragma unroll
    for (int i = 0; i < 8; i++)
        #pragma unroll
        for (int j = 0; j < 8; j++) acc[i][j] = 0.f;

    for (int k0 = 0; k0 < K; k0 += 16) {
        #pragma unroll
        for (int it = 0; it < 2; it++) {
            int f = tid + it * 256;            // 0..511 float4 slots
            int row = f >> 2;
            int c4  = (f & 3) << 2;
            float4 va = *reinterpret_cast<const float4*>(&A[(size_t)(m0 + row) * K + k0 + c4]);
            As[c4 + 0][row] = va.x; As[c4 + 1][row] = va.y;
            As[c4 + 2][row] = va.z; As[c4 + 3][row] = va.w;
            float4 vb = *reinterpret_cast<const float4*>(&B[(size_t)(n0 + row) * K + k0 + c4]);
            Bs[c4 + 0][row] = vb.x; Bs[c4 + 1][row] = vb.y;
            Bs[c4 + 2][row] = vb.z; Bs[c4 + 3][row] = vb.w;
        }
        __syncthreads();
        #pragma unroll
        for (int kk = 0; kk < 16; kk++) {
            float a[8], bb[8];
            #pragma unroll
            for (int i = 0; i < 8; i++) a[i]  = As[kk][ty + 16 * i];
            #pragma unroll
            for (int j = 0; j < 8; j++) bb[j] = Bs[kk][tx + 16 * j];
            #pragma unroll
            for (int i = 0; i < 8; i++)
                #pragma unroll
                for (int j = 0; j < 8; j++)
                    acc[i][j] = fmaf(a[i], bb[j], acc[i][j]);
        }
        __syncthreads();
    }

    #pragma unroll
    for (int i = 0; i < 8; i++) {
        int m = m0 + ty + 16 * i;
        #pragma unroll
        for (int j = 0; j < 8; j++) {
            int n = n0 + tx + 16 * j;
            float v = acc[i][j] + __ldg(&bias[n]);
            if (ACT == 1) v = (v > 0.f) ? v : 0.01f * v;   // leaky relu
            C[(size_t)m * Nn + n] = v;
        }
    }
}

// ---------------- 3. gather emb into zero-padded dense ----------------
__global__ void fill_dense(const int* __restrict__ si) {
    int idx4 = blockIdx.x * blockDim.x + threadIdx.x;   // over ROWS*EMB/4
    if (idx4 >= ROWS * EMB / 4) return;
    int idx = idx4 << 2;
    int r = idx / EMB, e = idx - r * EMB;
    int b = r >> 8, s = r & (MAXD - 1);
    int start = __ldg(&si[b]);
    int len   = __ldg(&si[b + 1]) - start;
    float4 v = make_float4(0.f, 0.f, 0.f, 0.f);
    if (s < len)
        v = *reinterpret_cast<const float4*>(&g_emb[(size_t)(start + s) * EMB + e]);
    *reinterpret_cast<float4*>(&g_dense[idx]) = v;
}

// ---------------- 5. scores = Q K^T / sqrt(hd), per (b,h) ----------------
__global__ __launch_bounds__(256) void scores_kernel() {
    int z = blockIdx.z;                    // b*8 + h
    int b = z >> 3, h = z & 7;
    const float* Qb = g_qkv + (size_t)b * MAXD * QKV_DIM + h * HD;
    const float* Kb = Qb + EMB;
    float* S = g_scores + (size_t)z * MAXD * MAXD;

    __shared__ float As[16][128];
    __shared__ float Bs[16][128];

    int m0 = blockIdx.y * 128;
    int n0 = blockIdx.x * 128;
    int tid = threadIdx.x;
    int tx = tid & 15, ty = tid >> 4;

    float acc[8][8];
    #pragma unroll
    for (int i = 0; i < 8; i++)
        #pragma unroll
        for (int j = 0; j < 8; j++) acc[i][j] = 0.f;

    for (int k0 = 0; k0 < HD; k0 += 16) {
        #pragma unroll
        for (int it = 0; it < 2; it++) {
            int f = tid + it * 256;
            int row = f >> 2;
            int c4  = (f & 3) << 2;
            float4 va = *reinterpret_cast<const float4*>(&Qb[(size_t)(m0 + row) * QKV_DIM + k0 + c4]);
            As[c4 + 0][row] = va.x; As[c4 + 1][row] = va.y;
            As[c4 + 2][row] = va.z; As[c4 + 3][row] = va.w;
            float4 vb = *reinterpret_cast<const float4*>(&Kb[(size_t)(n0 + row) * QKV_DIM + k0 + c4]);
            Bs[c4 + 0][row] = vb.x; Bs[c4 + 1][row] = vb.y;
            Bs[c4 + 2][row] = vb.z; Bs[c4 + 3][row] = vb.w;
        }
        __syncthreads();
        #pragma unroll
        for (int kk = 0; kk < 16; kk++) {
            float a[8], bb[8];
            #pragma unroll
            for (int i = 0; i < 8; i++) a[i]  = As[kk][ty + 16 * i];
            #pragma unroll
            for (int j = 0; j < 8; j++) bb[j] = Bs[kk][tx + 16 * j];
            #pragma unroll
            for (int i = 0; i < 8; i++)
                #pragma unroll
                for (int j = 0; j < 8; j++)
                    acc[i][j] = fmaf(a[i], bb[j], acc[i][j]);
        }
        __syncthreads();
    }

    #pragma unroll
    for (int i = 0; i < 8; i++) {
        int m = m0 + ty + 16 * i;
        #pragma unroll
        for (int j = 0; j < 8; j++) {
            int n = n0 + tx + 16 * j;
            S[(size_t)m * MAXD + n] = acc[i][j] * 0.125f;   // 1/sqrt(64)
        }
    }
}

// ---------------- 6. softmax over 256 keys, one warp per row ----------------
__global__ void softmax_kernel() {
    int gwarp = (blockIdx.x * blockDim.x + threadIdx.x) >> 5;
    int lane  = threadIdx.x & 31;
    if (gwarp >= BATCH * NH * MAXD) return;
    float* row = g_scores + (size_t)gwarp * MAXD;

    float v[8];
    float mx = -1e30f;
    #pragma unroll
    for (int i = 0; i < 8; i++) { v[i] = row[lane + 32 * i]; mx = fmaxf(mx, v[i]); }
    #pragma unroll
    for (int o = 16; o; o >>= 1) mx = fmaxf(mx, __shfl_xor_sync(0xffffffffu, mx, o));
    float s = 0.f;
    #pragma unroll
    for (int i = 0; i < 8; i++) { v[i] = __expf(v[i] - mx); s += v[i]; }
    #pragma unroll
    for (int o = 16; o; o >>= 1) s += __shfl_xor_sync(0xffffffffu, s, o);
    float inv = 1.f / s;
    #pragma unroll
    for (int i = 0; i < 8; i++) row[lane + 32 * i] = v[i] * inv;
}

// ---------------- 7. ctx = attn @ V, per (b,h) ----------------
__global__ __launch_bounds__(256) void ctx_kernel() {
    int z = blockIdx.y;
    int b = z >> 3, h = z & 7;
    int q0 = blockIdx.x * 64;
    const float* Attn = g_scores + (size_t)z * MAXD * MAXD;
    const float* V = g_qkv + (size_t)b * MAXD * QKV_DIM + 2 * EMB + h * HD;

    __shared__ float As[16][64];   // attn[kk][q]
    __shared__ float Bs[16][64];   // v[kk][d]

    int tid = threadIdx.x;
    int tx = tid & 15, ty = tid >> 4;

    float acc[4][4];
    #pragma unroll
    for (int i = 0; i < 4; i++)
        #pragma unroll
        for (int j = 0; j < 4; j++) acc[i][j] = 0.f;

    for (int k0 = 0; k0 < MAXD; k0 += 16) {
        {   // A tile: 64 q x 16 k = 256 float4
            int row = tid >> 2;
            int c4  = (tid & 3) << 2;
            float4 va = *reinterpret_cast<const float4*>(&Attn[(size_t)(q0 + row) * MAXD + k0 + c4]);
            As[c4 + 0][row] = va.x; As[c4 + 1][row] = va.y;
            As[c4 + 2][row] = va.z; As[c4 + 3][row] = va.w;
        }
        {   // B tile: 16 k x 64 d
            int kk = tid >> 4;
            int d4 = (tid & 15) << 2;
            float4 vb = *reinterpret_cast<const float4*>(&V[(size_t)(k0 + kk) * QKV_DIM + d4]);
            Bs[kk][d4 + 0] = vb.x; Bs[kk][d4 + 1] = vb.y;
            Bs[kk][d4 + 2] = vb.z; Bs[kk][d4 + 3] = vb.w;
        }
        __syncthreads();
        #pragma unroll
        for (int kk = 0; kk < 16; kk++) {
            float a[4], bb[4];
            #pragma unroll
            for (int i = 0; i < 4; i++) a[i]  = As[kk][ty + 16 * i];
            #pragma unroll
            for (int j = 0; j < 4; j++) bb[j] = Bs[kk][tx + 16 * j];
            #pragma unroll
            for (int i = 0; i < 4; i++)
                #pragma unroll
                for (int j = 0; j < 4; j++)
                    acc[i][j] = fmaf(a[i], bb[j], acc[i][j]);
        }
        __syncthreads();
    }

    #pragma unroll
    for (int i = 0; i < 4; i++) {
        int q = q0 + ty + 16 * i;
        #pragma unroll
        for (int j = 0; j < 4; j++) {
            int d = tx + 16 * j;
            g_ctx[(size_t)(b * MAXD + q) * EMB + h * HD + d] = acc[i][j];
        }
    }
}

// ---------------- 9. residual + LayerNorm ----------------
__device__ __forceinline__ float block_sum_512(float s, float* sm) {
    int t = threadIdx.x;
    #pragma unroll
    for (int o = 16; o; o >>= 1) s += __shfl_xor_sync(0xffffffffu, s, o);
    __syncthreads();
    if ((t & 31) == 0) sm[t >> 5] = s;
    __syncthreads();
    float x = 0.f;
    #pragma unroll
    for (int i = 0; i < 8; i++) x += sm[i];
    return x;
}

__global__ void ln_kernel(const float* __restrict__ gamma, const float* __restrict__ beta) {
    __shared__ float sm[8];
    int r = blockIdx.x;
    int t = threadIdx.x;                      // 256 threads, 2 elems each
    size_t base = (size_t)r * EMB;
    float v0 = g_mha[base + t]       + g_dense[base + t];
    float v1 = g_mha[base + t + 256] + g_dense[base + t + 256];

    float tot = block_sum_512(v0 + v1, sm);
    float mu = tot * (1.f / (float)EMB);
    float d0 = v0 - mu, d1 = v1 - mu;
    float var = block_sum_512(d0 * d0 + d1 * d1, sm) * (1.f / (float)EMB);
    float w = rsqrtf(var + LN_EPS);
    g_norm[base + t]       = d0 * w * __ldg(&gamma[t])       + __ldg(&beta[t]);
    g_norm[base + t + 256] = d1 * w * __ldg(&gamma[t + 256]) + __ldg(&beta[t + 256]);
}

// ---------------- 10. out = [emb | gathered norm] ----------------
__global__ void concat_kernel(const int* __restrict__ si, float* __restrict__ out) {
    int idx = blockIdx.x * blockDim.x + threadIdx.x;   // over N_TOK*1024
    if (idx >= N_TOK * 1024) return;
    int n = idx >> 10, e = idx & 1023;
    float v;
    if (e < EMB) {
        v = g_emb[(size_t)n * EMB + e];
    } else {
        int b = find_batch(si, n);
        int s = n - __ldg(&si[b]);
        v = g_norm[(size_t)(b * MAXD + s) * EMB + (e - EMB)];
    }
    out[idx] = v;
}

// ---------------- launch ----------------
extern "C" void kernel_launch(void* const* d_in, const int* in_sizes, int n_in,
                              void* d_out, int out_size) {
    const float* states = (const float*)d_in[0];
    const int*   si     = (const int*)  d_in[1];
    const float* W1     = (const float*)d_in[2];
    const float* b1     = (const float*)d_in[3];
    const float* in_w   = (const float*)d_in[4];
    const float* in_b   = (const float*)d_in[5];
    const float* out_w  = (const float*)d_in[6];
    const float* out_b  = (const float*)d_in[7];
    const float* gamma  = (const float*)d_in[8];
    const float* beta   = (const float*)d_in[9];
    float* out = (float*)d_out;

    build_x<<<(N_TOK * IN_DIM + 255) / 256, 256>>>(states, si);

    // emb = leaky_relu(x @ W1^T + b1)
    gemm_nt<1, 0><<<dim3(EMB / 128, N_TOK / 128), 256>>>(W1, b1, N_TOK, EMB, IN_DIM);

    fill_dense<<<(ROWS * EMB / 4 + 255) / 256, 256>>>(si);

    // qkv = dense @ in_w^T + in_b
    gemm_nt<0, 1><<<dim3(QKV_DIM / 128, ROWS / 128), 256>>>(in_w, in_b, ROWS, QKV_DIM, EMB);

    scores_kernel<<<dim3(MAXD / 128, MAXD / 128, BATCH * NH), 256>>>();

    softmax_kernel<<<(BATCH * NH * MAXD) / 8, 256>>>();   // 8 warps/block

    ctx_kernel<<<dim3(MAXD / 64, BATCH * NH), 256>>>();

    // mha = ctx @ out_w^T + out_b
    gemm_nt<0, 2><<<dim3(EMB / 128, ROWS / 128), 256>>>(out_w, out_b, ROWS, EMB, EMB);

    ln_kernel<<<ROWS, 256>>>(gamma, beta);

    concat_kernel<<<(N_TOK * 1024 + 255) / 256, 256>>>(si, out);
}

// round 2
// speedup vs baseline: 1.0016x; 1.0016x over previous
#include <cuda_runtime.h>
#include <math.h>
#include <stdint.h>

// ---------------- static problem shape (from setup_inputs) ----------------
#define N_TOK   12288
#define BATCH   64
#define MAXD    256
#define DEV     448
#define PE_DIM  64
#define EMB     512
#define IN_DIM  512            // DEV + PE_DIM
#define NH      8
#define HD      64
#define ROWS    (BATCH*MAXD)   // 16384 padded rows
#define QKV_DIM (3*EMB)        // 1536
#define LN_EPS  1e-5f

// ---------------- scratch (static device globals; no allocs) ----------------
__device__ float g_x    [(size_t)N_TOK*IN_DIM];
__device__ float g_emb  [(size_t)N_TOK*EMB];
__device__ float g_dense[(size_t)ROWS*EMB];
__device__ float g_qkv  [(size_t)ROWS*QKV_DIM];
__device__ float g_scores[(size_t)BATCH*NH*MAXD*MAXD];
__device__ float g_ctx  [(size_t)ROWS*EMB];
__device__ float g_mha  [(size_t)ROWS*EMB];
__device__ float g_norm [(size_t)ROWS*EMB];

// ---------------- helpers ----------------
__device__ __forceinline__ int find_batch(const int* __restrict__ si, int n) {
    int lo = 0, hi = BATCH;
    while (hi - lo > 1) {
        int mid = (lo + hi) >> 1;
        if (__ldg(&si[mid]) <= n) lo = mid; else hi = mid;
    }
    return lo;
}

// ---------------- 1. build x = [states | PE] ----------------
__global__ void build_x(const float* __restrict__ states, const int* __restrict__ si) {
    int idx = blockIdx.x * blockDim.x + threadIdx.x;
    if (idx >= N_TOK * IN_DIM) return;
    int n = idx / IN_DIM, c = idx - n * IN_DIM;
    float v;
    if (c < DEV) {
        v = states[(size_t)n * DEV + c];
    } else {
        int b = find_batch(si, n);
        int pos = n - __ldg(&si[b]) + 1;             // 1-based
        int j = c - DEV;
        int i2 = (j >> 1) << 1;                      // 0,0,2,2,4,4,...
        float freq = expf((float)i2 * (-9.210340371976184f / (float)PE_DIM));
        float ang = (float)pos * freq;
        v = (j & 1) ? cosf(ang) : sinf(ang);
    }
    g_x[idx] = v;
}

// ---------------- 2/4/8. generic NT GEMM: C = act(A * B^T + bias) ----------------
// 128x128 block tile, BK=16, 256 threads, 8x8 micro-tile.
// WHICH selects scratch A/C:  0: g_x->g_emb   1: g_dense->g_qkv   2: g_ctx->g_mha
template<int ACT, int WHICH>
__global__ __launch_bounds__(256) void gemm_nt(const float* __restrict__ B,
                                               const float* __restrict__ bias,
                                               int M, int Nn, int K) {
    const float* A = (WHICH == 0) ? g_x : (WHICH == 1) ? g_dense : g_ctx;
    float*       C = (WHICH == 0) ? g_emb : (WHICH == 1) ? g_qkv : g_mha;

    __shared__ float As[16][128];
    __shared__ float Bs[16][128];

    int m0 = blockIdx.y * 128;
    int n0 = blockIdx.x * 128;
    int tid = threadIdx.x;
    int tx = tid & 15, ty = tid >> 4;

    float acc[8][8];
    #pragma unroll
    for (int i = 0; i < 8; i++)
        #pragma unroll
        for (int j = 0; j < 8; j++) acc[i][j] = 0.f;

    for (int k0 = 0; k0 < K; k0 += 16) {
        #pragma unroll
        for (int it = 0; it < 2; it++) {
            int f = tid + it * 256;            // 0..511 float4 slots
            int row = f >> 2;
            int c4  = (f & 3) << 2;
            float4 va = *reinterpret_cast<const float4*>(&A[(size_t)(m0 + row) * K + k0 + c4]);
            As[c4 + 0][row] = va.x; As[c4 + 1][row] = va.y;
            As[c4 + 2][row] = va.z; As[c4 + 3][row] = va.w;
            float4 vb = *reinterpret_cast<const float4*>(&B[(size_t)(n0 + row) * K + k0 + c4]);
            Bs[c4 + 0][row] = vb.x; Bs[c4 + 1][row] = vb.y;
            Bs[c4 + 2][row] = vb.z; Bs[c4 + 3][row] = vb.w;
        }
        __syncthreads();
        #pragma unroll
        for (int kk = 0; kk < 16; kk++) {
            float a[8], bb[8];
            #pragma unroll
            for (int i = 0; i < 8; i++) a[i]  = As[kk][ty + 16 * i];
            #pragma unroll
            for (int j = 0; j < 8; j++) bb[j] = Bs[kk][tx + 16 * j];
            #pragma unroll
            for (int i = 0; i < 8; i++)
                #pragma unroll
                for (int j = 0; j < 8; j++)
                    acc[i][j] = fmaf(a[i], bb[j], acc[i][j]);
        }
        __syncthreads();
    }

    #pragma unroll
    for (int i = 0; i < 8; i++) {
        int m = m0 + ty + 16 * i;
        #pragma unroll
        for (int j = 0; j < 8; j++) {
            int n = n0 + tx + 16 * j;
            float v = acc[i][j] + __ldg(&bias[n]);
            if (ACT == 1) v = (v > 0.f) ? v : 0.01f * v;   // leaky relu
            C[(size_t)m * Nn + n] = v;
        }
    }
}

// ---------------- 3. gather emb into zero-padded dense ----------------
__global__ void fill_dense(const int* __restrict__ si) {
    int idx4 = blockIdx.x * blockDim.x + threadIdx.x;   // over ROWS*EMB/4
    if (idx4 >= ROWS * EMB / 4) return;
    int idx = idx4 << 2;
    int r = idx / EMB, e = idx - r * EMB;
    int b = r >> 8, s = r & (MAXD - 1);
    int start = __ldg(&si[b]);
    int len   = __ldg(&si[b + 1]) - start;
    float4 v = make_float4(0.f, 0.f, 0.f, 0.f);
    if (s < len)
        v = *reinterpret_cast<const float4*>(&g_emb[(size_t)(start + s) * EMB + e]);
    *reinterpret_cast<float4*>(&g_dense[idx]) = v;
}

// ---------------- 5. scores = Q K^T / sqrt(hd), per (b,h) ----------------
__global__ __launch_bounds__(256) void scores_kernel() {
    int z = blockIdx.z;                    // b*8 + h
    int b = z >> 3, h = z & 7;
    const float* Qb = g_qkv + (size_t)b * MAXD * QKV_DIM + h * HD;
    const float* Kb = Qb + EMB;
    float* S = g_scores + (size_t)z * MAXD * MAXD;

    __shared__ float As[16][128];
    __shared__ float Bs[16][128];

    int m0 = blockIdx.y * 128;
    int n0 = blockIdx.x * 128;
    int tid = threadIdx.x;
    int tx = tid & 15, ty = tid >> 4;

    float acc[8][8];
    #pragma unroll
    for (int i = 0; i < 8; i++)
        #pragma unroll
        for (int j = 0; j < 8; j++) acc[i][j] = 0.f;

    for (int k0 = 0; k0 < HD; k0 += 16) {
        #pragma unroll
        for (int it = 0; it < 2; it++) {
            int f = tid + it * 256;
            int row = f >> 2;
            int c4  = (f & 3) << 2;
            float4 va = *reinterpret_cast<const float4*>(&Qb[(size_t)(m0 + row) * QKV_DIM + k0 + c4]);
            As[c4 + 0][row] = va.x; As[c4 + 1][row] = va.y;
            As[c4 + 2][row] = va.z; As[c4 + 3][row] = va.w;
            float4 vb = *reinterpret_cast<const float4*>(&Kb[(size_t)(n0 + row) * QKV_DIM + k0 + c4]);
            Bs[c4 + 0][row] = vb.x; Bs[c4 + 1][row] = vb.y;
            Bs[c4 + 2][row] = vb.z; Bs[c4 + 3][row] = vb.w;
        }
        __syncthreads();
        #pragma unroll
        for (int kk = 0; kk < 16; kk++) {
            float a[8], bb[8];
            #pragma unroll
            for (int i = 0; i < 8; i++) a[i]  = As[kk][ty + 16 * i];
            #pragma unroll
            for (int j = 0; j < 8; j++) bb[j] = Bs[kk][tx + 16 * j];
            #pragma unroll
            for (int i = 0; i < 8; i++)
                #pragma unroll
                for (int j = 0; j < 8; j++)
                    acc[i][j] = fmaf(a[i], bb[j], acc[i][j]);
        }
        __syncthreads();
    }

    #pragma unroll
    for (int i = 0; i < 8; i++) {
        int m = m0 + ty + 16 * i;
        #pragma unroll
        for (int j = 0; j < 8; j++) {
            int n = n0 + tx + 16 * j;
            S[(size_t)m * MAXD + n] = acc[i][j] * 0.125f;   // 1/sqrt(64)
        }
    }
}

// ---------------- 6. softmax over 256 keys, one warp per row ----------------
__global__ void softmax_kernel() {
    int gwarp = (blockIdx.x * blockDim.x + threadIdx.x) >> 5;
    int lane  = threadIdx.x & 31;
    if (gwarp >= BATCH * NH * MAXD) return;
    float* row = g_scores + (size_t)gwarp * MAXD;

    float v[8];
    float mx = -1e30f;
    #pragma unroll
    for (int i = 0; i < 8; i++) { v[i] = row[lane + 32 * i]; mx = fmaxf(mx, v[i]); }
    #pragma unroll
    for (int o = 16; o; o >>= 1) mx = fmaxf(mx, __shfl_xor_sync(0xffffffffu, mx, o));
    float s = 0.f;
    #pragma unroll
    for (int i = 0; i < 8; i++) { v[i] = __expf(v[i] - mx); s += v[i]; }
    #pragma unroll
    for (int o = 16; o; o >>= 1) s += __shfl_xor_sync(0xffffffffu, s, o);
    float inv = 1.f / s;
    #pragma unroll
    for (int i = 0; i < 8; i++) row[lane + 32 * i] = v[i] * inv;
}

// ---------------- 7. ctx = attn @ V, per (b,h) ----------------
__global__ __launch_bounds__(256) void ctx_kernel() {
    int z = blockIdx.y;
    int b = z >> 3, h = z & 7;
    int q0 = blockIdx.x * 64;
    const float* Attn = g_scores + (size_t)z * MAXD * MAXD;
    const float* V = g_qkv + (size_t)b * MAXD * QKV_DIM + 2 * EMB + h * HD;

    __shared__ float As[16][64];   // attn[kk][q]
    __shared__ float Bs[16][64];   // v[kk][d]

    int tid = threadIdx.x;
    int tx = tid & 15, ty = tid >> 4;

    float acc[4][4];
    #pragma unroll
    for (int i = 0; i < 4; i++)
        #pragma unroll
        for (int j = 0; j < 4; j++) acc[i][j] = 0.f;

    for (int k0 = 0; k0 < MAXD; k0 += 16) {
        {   // A tile: 64 q x 16 k = 256 float4
            int row = tid >> 2;
            int c4  = (tid & 3) << 2;
            float4 va = *reinterpret_cast<const float4*>(&Attn[(size_t)(q0 + row) * MAXD + k0 + c4]);
            As[c4 + 0][row] = va.x; As[c4 + 1][row] = va.y;
            As[c4 + 2][row] = va.z; As[c4 + 3][row] = va.w;
        }
        {   // B tile: 16 k x 64 d
            int kk = tid >> 4;
            int d4 = (tid & 15) << 2;
            float4 vb = *reinterpret_cast<const float4*>(&V[(size_t)(k0 + kk) * QKV_DIM + d4]);
            Bs[kk][d4 + 0] = vb.x; Bs[kk][d4 + 1] = vb.y;
            Bs[kk][d4 + 2] = vb.z; Bs[kk][d4 + 3] = vb.w;
        }
        __syncthreads();
        #pragma unroll
        for (int kk = 0; kk < 16; kk++) {
            float a[4], bb[4];
            #pragma unroll
            for (int i = 0; i < 4; i++) a[i]  = As[kk][ty + 16 * i];
            #pragma unroll
            for (int j = 0; j < 4; j++) bb[j] = Bs[kk][tx + 16 * j];
            #pragma unroll
            for (int i = 0; i < 4; i++)
                #pragma unroll
                for (int j = 0; j < 4; j++)
                    acc[i][j] = fmaf(a[i], bb[j], acc[i][j]);
        }
        __syncthreads();
    }

    #pragma unroll
    for (int i = 0; i < 4; i++) {
        int q = q0 + ty + 16 * i;
        #pragma unroll
        for (int j = 0; j < 4; j++) {
            int d = tx + 16 * j;
            g_ctx[(size_t)(b * MAXD + q) * EMB + h * HD + d] = acc[i][j];
        }
    }
}

// ---------------- 9. residual + LayerNorm ----------------
__device__ __forceinline__ float block_sum_512(float s, float* sm) {
    int t = threadIdx.x;
    #pragma unroll
    for (int o = 16; o; o >>= 1) s += __shfl_xor_sync(0xffffffffu, s, o);
    __syncthreads();
    if ((t & 31) == 0) sm[t >> 5] = s;
    __syncthreads();
    float x = 0.f;
    #pragma unroll
    for (int i = 0; i < 8; i++) x += sm[i];
    return x;
}

__global__ void ln_kernel(const float* __restrict__ gamma, const float* __restrict__ beta) {
    __shared__ float sm[8];
    int r = blockIdx.x;
    int t = threadIdx.x;                      // 256 threads, 2 elems each
    size_t base = (size_t)r * EMB;
    float v0 = g_mha[base + t]       + g_dense[base + t];
    float v1 = g_mha[base + t + 256] + g_dense[base + t + 256];

    float tot = block_sum_512(v0 + v1, sm);
    float mu = tot * (1.f / (float)EMB);
    float d0 = v0 - mu, d1 = v1 - mu;
    float var = block_sum_512(d0 * d0 + d1 * d1, sm) * (1.f / (float)EMB);
    float w = rsqrtf(var + LN_EPS);
    g_norm[base + t]       = d0 * w * __ldg(&gamma[t])       + __ldg(&beta[t]);
    g_norm[base + t + 256] = d1 * w * __ldg(&gamma[t + 256]) + __ldg(&beta[t + 256]);
}

// ---------------- 10. out = [emb | gathered norm] ----------------
__global__ void concat_kernel(const int* __restrict__ si, float* __restrict__ out) {
    int idx = blockIdx.x * blockDim.x + threadIdx.x;   // over N_TOK*1024
    if (idx >= N_TOK * 1024) return;
    int n = idx >> 10, e = idx & 1023;
    float v;
    if (e < EMB) {
        v = g_emb[(size_t)n * EMB + e];
    } else {
        int b = find_batch(si, n);
        int s = n - __ldg(&si[b]);
        v = g_norm[(size_t)(b * MAXD + s) * EMB + (e - EMB)];
    }
    out[idx] = v;
}

// ---------------- launch ----------------
extern "C" void kernel_launch(void* const* d_in, const int* in_sizes, int n_in,
                              void* d_out, int out_size) {
    const float* states = (const float*)d_in[0];
    const int*   si     = (const int*)  d_in[1];
    const float* W1     = (const float*)d_in[2];
    const float* b1     = (const float*)d_in[3];
    const float* in_w   = (const float*)d_in[4];
    const float* in_b   = (const float*)d_in[5];
    const float* out_w  = (const float*)d_in[6];
    const float* out_b  = (const float*)d_in[7];
    const float* gamma  = (const float*)d_in[8];
    const float* beta   = (const float*)d_in[9];
    float* out = (float*)d_out;

    build_x<<<(N_TOK * IN_DIM + 255) / 256, 256>>>(states, si);

    // emb = leaky_relu(x @ W1^T + b1)
    gemm_nt<1, 0><<<dim3(EMB / 128, N_TOK / 128), 256>>>(W1, b1, N_TOK, EMB, IN_DIM);

    fill_dense<<<(ROWS * EMB / 4 + 255) / 256, 256>>>(si);

    // qkv = dense @ in_w^T + in_b
    gemm_nt<0, 1><<<dim3(QKV_DIM / 128, ROWS / 128), 256>>>(in_w, in_b, ROWS, QKV_DIM, EMB);

    scores_kernel<<<dim3(MAXD / 128, MAXD / 128, BATCH * NH), 256>>>();

    softmax_kernel<<<(BATCH * NH * MAXD) / 8, 256>>>();   // 8 warps/block

    ctx_kernel<<<dim3(MAXD / 64, BATCH * NH), 256>>>();

    // mha = ctx @ out_w^T + out_b
    gemm_nt<0, 2><<<dim3(EMB / 128, ROWS / 128), 256>>>(out_w, out_b, ROWS, EMB, EMB);

    ln_kernel<<<ROWS, 256>>>(gamma, beta);

    concat_kernel<<<(N_TOK * 1024 + 255) / 256, 256>>>(si, out);
}